// round 2
// baseline (speedup 1.0000x reference)
#include <cuda_runtime.h>
#include <math.h>

// Problem constants
#define B_    4
#define S_    2048
#define E_    1024
#define H_    8
#define D_    128
#define UVQK_ 4096
#define MTOT  (B_ * S_)   // 8192 rows

#define ALPHA_F 0.08838834764831845f   // 1/sqrt(128)
#define INV_S_F (1.0f / 2048.0f)

// ---------------------------------------------------------------------------
// Scratch (device globals — no allocation allowed)
// ---------------------------------------------------------------------------
__device__ float g_xn[(size_t)MTOT * E_];       //  32 MB  normed_x
__device__ float g_uvqk[(size_t)MTOT * UVQK_];  // 128 MB  u|v|q|k projections
__device__ float g_attn[(size_t)MTOT * E_];     //  32 MB  attention output
__device__ float g_nattn[(size_t)MTOT * E_];    //  32 MB  layernormed attn

__device__ __forceinline__ float silu_f(float v) {
    return v / (1.0f + __expf(-v));
}

// ---------------------------------------------------------------------------
// LayerNorm: one block per row of 1024 floats, 256 threads (float4 each)
// ---------------------------------------------------------------------------
__device__ __forceinline__ void ln_row(const float* __restrict__ in,
                                       const float* __restrict__ sc,
                                       const float* __restrict__ bi,
                                       float* __restrict__ out) {
    __shared__ float red[16];
    const size_t row = blockIdx.x;
    const int tid = threadIdx.x;
    const float4 v = ((const float4*)(in + row * E_))[tid];

    float s  = v.x + v.y + v.z + v.w;
    float sq = v.x * v.x + v.y * v.y + v.z * v.z + v.w * v.w;
#pragma unroll
    for (int o = 16; o > 0; o >>= 1) {
        s  += __shfl_xor_sync(0xFFFFFFFFu, s, o);
        sq += __shfl_xor_sync(0xFFFFFFFFu, sq, o);
    }
    const int warp = tid >> 5, lane = tid & 31;
    if (lane == 0) { red[warp] = s; red[8 + warp] = sq; }
    __syncthreads();
    if (tid < 32) {
        float ss = (lane < 8) ? red[lane] : 0.0f;
        float qq = (lane < 8) ? red[8 + lane] : 0.0f;
#pragma unroll
        for (int o = 4; o > 0; o >>= 1) {
            ss += __shfl_xor_sync(0xFFFFFFFFu, ss, o);
            qq += __shfl_xor_sync(0xFFFFFFFFu, qq, o);
        }
        if (lane == 0) { red[0] = ss; red[1] = qq; }
    }
    __syncthreads();
    const float mean = red[0] * (1.0f / (float)E_);
    const float var  = red[1] * (1.0f / (float)E_) - mean * mean;
    const float r    = rsqrtf(var + 1e-6f);

    const float4 scv = ((const float4*)sc)[tid];
    const float4 biv = ((const float4*)bi)[tid];
    float4 o;
    o.x = (v.x - mean) * r * scv.x + biv.x;
    o.y = (v.y - mean) * r * scv.y + biv.y;
    o.z = (v.z - mean) * r * scv.z + biv.z;
    o.w = (v.w - mean) * r * scv.w + biv.w;
    ((float4*)(out + row * E_))[tid] = o;
}

__global__ __launch_bounds__(256) void ln_in_kernel(const float* __restrict__ x,
                                                    const float* __restrict__ sc,
                                                    const float* __restrict__ bi) {
    ln_row(x, sc, bi, g_xn);
}

__global__ __launch_bounds__(256) void ln_attn_kernel(const float* __restrict__ sc,
                                                      const float* __restrict__ bi) {
    ln_row(g_attn, sc, bi, g_nattn);
}

// ---------------------------------------------------------------------------
// GEMM1: g_uvqk[8192,4096] = g_xn[8192,1024] @ W[1024,4096] + beta
// 128x128 tile, BK=8, 256 threads, 8x8 per thread
// ---------------------------------------------------------------------------
__global__ __launch_bounds__(256) void gemm_uvqk_kernel(const float* __restrict__ W,
                                                        const float* __restrict__ beta) {
    constexpr int K = E_;      // 1024
    constexpr int N = UVQK_;   // 4096
    __shared__ float As[8][128];
    __shared__ float Bs[8][128];

    const int tid  = threadIdx.x;
    const int row0 = blockIdx.y * 128;
    const int col0 = blockIdx.x * 128;

    const int arow = tid >> 1;
    const int acol = (tid & 1) << 2;
    const int brow = tid >> 5;
    const int bcol = (tid & 31) << 2;
    const int tx = tid & 15, ty = tid >> 4;

    const float* Aptr = g_xn + (size_t)(row0 + arow) * K + acol;
    const float* Bptr = W + (size_t)brow * N + col0 + bcol;

    float acc[8][8];
#pragma unroll
    for (int i = 0; i < 8; i++)
#pragma unroll
        for (int j = 0; j < 8; j++) acc[i][j] = 0.0f;

    for (int k0 = 0; k0 < K; k0 += 8) {
        const float4 av = *(const float4*)(Aptr + k0);
        As[acol + 0][arow] = av.x;
        As[acol + 1][arow] = av.y;
        As[acol + 2][arow] = av.z;
        As[acol + 3][arow] = av.w;
        *(float4*)&Bs[brow][bcol] = *(const float4*)(Bptr + (size_t)k0 * N);
        __syncthreads();
#pragma unroll
        for (int kk = 0; kk < 8; kk++) {
            const float4 a0 = *(const float4*)&As[kk][ty * 8];
            const float4 a1 = *(const float4*)&As[kk][ty * 8 + 4];
            const float4 b0 = *(const float4*)&Bs[kk][tx * 8];
            const float4 b1 = *(const float4*)&Bs[kk][tx * 8 + 4];
            const float ar[8] = {a0.x, a0.y, a0.z, a0.w, a1.x, a1.y, a1.z, a1.w};
            const float br[8] = {b0.x, b0.y, b0.z, b0.w, b1.x, b1.y, b1.z, b1.w};
#pragma unroll
            for (int i = 0; i < 8; i++)
#pragma unroll
                for (int j = 0; j < 8; j++)
                    acc[i][j] = fmaf(ar[i], br[j], acc[i][j]);
        }
        __syncthreads();
    }

#pragma unroll
    for (int i = 0; i < 8; i++) {
        const int r = row0 + ty * 8 + i;
        float* Cp = g_uvqk + (size_t)r * N + col0 + tx * 8;
        const float* bp = beta + col0 + tx * 8;
#pragma unroll
        for (int j = 0; j < 8; j += 4) {
            const float4 bb = *(const float4*)(bp + j);
            float4 o;
            o.x = acc[i][j + 0] + bb.x;
            o.y = acc[i][j + 1] + bb.y;
            o.z = acc[i][j + 2] + bb.z;
            o.w = acc[i][j + 3] + bb.w;
            *(float4*)(Cp + j) = o;
        }
    }
}

// ---------------------------------------------------------------------------
// Attention: silu attention, no softmax state needed.
//   attn[b,q,h,:] = sum_k silu(q.k * alpha)/S * mask * v[k]
// One CTA per (64 q-rows, h, b). Causal tile skip: only k-tiles <= q-tile.
// smem: qT[128][68] (transposed, loaded once), k[64][132], v[64][128], s[64][68]
// ---------------------------------------------------------------------------
#define QS 68
#define KS 132
#define VS 128
#define SS 68
#define ATTN_SMEM ((128 * QS + 64 * KS + 64 * VS + 64 * SS) * sizeof(float))

__global__ __launch_bounds__(256) void attn_kernel(const int* __restrict__ num_targets) {
    extern __shared__ float sm[];
    float* qT  = sm;                       // 128 x QS
    float* k_s = qT + 128 * QS;            // 64 x KS
    float* v_s = k_s + 64 * KS;            // 64 x VS
    float* s_s = v_s + 64 * VS;            // 64 x SS

    const int b  = blockIdx.z;
    const int h  = blockIdx.y;
    const int q0 = blockIdx.x * 64;
    const int tid = threadIdx.x;
    const int limit = S_ - num_targets[b];

    const float* base = g_uvqk + (size_t)b * S_ * UVQK_;

    // Load q tile transposed (once per block). Coalesced global read,
    // scattered smem store (paid once).
    for (int i = tid; i < 64 * 32; i += 256) {
        const int row = i >> 5;
        const int c4  = (i & 31) << 2;
        const float4 v = *(const float4*)&base[(size_t)(q0 + row) * UVQK_ + 2048 + h * D_ + c4];
        qT[(c4 + 0) * QS + row] = v.x;
        qT[(c4 + 1) * QS + row] = v.y;
        qT[(c4 + 2) * QS + row] = v.z;
        qT[(c4 + 3) * QS + row] = v.w;
    }

    float acc[4][8];
#pragma unroll
    for (int i = 0; i < 4; i++)
#pragma unroll
        for (int j = 0; j < 8; j++) acc[i][j] = 0.0f;

    const int tx = tid & 15, ty = tid >> 4;
    const int ntile = (q0 >> 6) + 1;   // causal: k-tiles up through q-tile

    for (int t = 0; t < ntile; t++) {
        const int k0 = t * 64;
        __syncthreads();   // protect smem reuse (also covers qT on t==0)
        for (int i = tid; i < 64 * 32; i += 256) {
            const int row = i >> 5;
            const int c4  = (i & 31) << 2;
            const float* rb = &base[(size_t)(k0 + row) * UVQK_ + h * D_ + c4];
            *(float4*)&k_s[row * KS + c4] = *(const float4*)(rb + 3072);  // k_proj
            *(float4*)&v_s[row * VS + c4] = *(const float4*)(rb + 1024);  // v_proj
        }
        __syncthreads();

        // Stage 1: scores. Thread owns rows i = tx*4.., cols j = ty*4..
        float sc[4][4];
#pragma unroll
        for (int i = 0; i < 4; i++)
#pragma unroll
            for (int j = 0; j < 4; j++) sc[i][j] = 0.0f;

        for (int d = 0; d < D_; d += 4) {
            float4 kv[4];
#pragma unroll
            for (int jj = 0; jj < 4; jj++)
                kv[jj] = *(const float4*)&k_s[(ty * 4 + jj) * KS + d];
#pragma unroll
            for (int dd = 0; dd < 4; dd++) {
                const float4 qv = *(const float4*)&qT[(d + dd) * QS + tx * 4];
                const float qa[4] = {qv.x, qv.y, qv.z, qv.w};
#pragma unroll
                for (int jj = 0; jj < 4; jj++) {
                    const float kc = (dd == 0) ? kv[jj].x : (dd == 1) ? kv[jj].y
                                   : (dd == 2) ? kv[jj].z : kv[jj].w;
#pragma unroll
                    for (int ii = 0; ii < 4; ii++)
                        sc[ii][jj] = fmaf(qa[ii], kc, sc[ii][jj]);
                }
            }
        }

        // silu + mask + store scores to smem
#pragma unroll
        for (int ii = 0; ii < 4; ii++) {
            const int qg = q0 + tx * 4 + ii;
            const int iq = min(qg, limit);
            float4 so;
            float* soc = &so.x;
#pragma unroll
            for (int jj = 0; jj < 4; jj++) {
                const int kg = k0 + ty * 4 + jj;
                const int ik = min(kg, limit);
                const bool keep = (qg == kg) || (iq > ik);
                const float v = sc[ii][jj] * ALPHA_F;
                soc[jj] = keep ? silu_f(v) * INV_S_F : 0.0f;
            }
            *(float4*)&s_s[(tx * 4 + ii) * SS + ty * 4] = so;
        }
        __syncthreads();

        // Stage 2: acc += s @ v. Thread owns rows i = ty*4.., cols c = tx*8..
#pragma unroll 8
        for (int j = 0; j < 64; j++) {
            float sv[4];
#pragma unroll
            for (int ii = 0; ii < 4; ii++)
                sv[ii] = s_s[(ty * 4 + ii) * SS + j];
            const float4 va = *(const float4*)&v_s[j * VS + tx * 8];
            const float4 vb = *(const float4*)&v_s[j * VS + tx * 8 + 4];
#pragma unroll
            for (int ii = 0; ii < 4; ii++) {
                acc[ii][0] = fmaf(sv[ii], va.x, acc[ii][0]);
                acc[ii][1] = fmaf(sv[ii], va.y, acc[ii][1]);
                acc[ii][2] = fmaf(sv[ii], va.z, acc[ii][2]);
                acc[ii][3] = fmaf(sv[ii], va.w, acc[ii][3]);
                acc[ii][4] = fmaf(sv[ii], vb.x, acc[ii][4]);
                acc[ii][5] = fmaf(sv[ii], vb.y, acc[ii][5]);
                acc[ii][6] = fmaf(sv[ii], vb.z, acc[ii][6]);
                acc[ii][7] = fmaf(sv[ii], vb.w, acc[ii][7]);
            }
        }
    }

    // Write attn output: (B*S, H*D) layout
#pragma unroll
    for (int ii = 0; ii < 4; ii++) {
        const int row = q0 + ty * 4 + ii;
        float* op = g_attn + (size_t)(b * S_ + row) * E_ + h * D_ + tx * 8;
        float4 o0 = {acc[ii][0], acc[ii][1], acc[ii][2], acc[ii][3]};
        float4 o1 = {acc[ii][4], acc[ii][5], acc[ii][6], acc[ii][7]};
        *(float4*)(op)     = o0;
        *(float4*)(op + 4) = o1;
    }
}

// ---------------------------------------------------------------------------
// GEMM2: out[8192,1024] = x + A[8192,3072] @ W2[3072,1024]
// A assembled on the fly:  k<1024: silu(uvqk[:, k])
//                          k<2048: attn[:, k-1024]
//                          else  : silu(uvqk[:, k-2048]) * nattn[:, k-2048]
// ---------------------------------------------------------------------------
__global__ __launch_bounds__(256) void gemm_out_kernel(const float* __restrict__ W2,
                                                       const float* __restrict__ x,
                                                       float* __restrict__ out) {
    constexpr int K = 3072;
    constexpr int N = E_;   // 1024
    __shared__ float As[8][128];
    __shared__ float Bs[8][128];

    const int tid  = threadIdx.x;
    const int row0 = blockIdx.y * 128;
    const int col0 = blockIdx.x * 128;

    const int arow = tid >> 1;
    const int acol = (tid & 1) << 2;
    const int brow = tid >> 5;
    const int bcol = (tid & 31) << 2;
    const int tx = tid & 15, ty = tid >> 4;

    const int m = row0 + arow;
    const float* Bptr = W2 + (size_t)brow * N + col0 + bcol;

    float acc[8][8];
#pragma unroll
    for (int i = 0; i < 8; i++)
#pragma unroll
        for (int j = 0; j < 8; j++) acc[i][j] = 0.0f;

    for (int k0 = 0; k0 < K; k0 += 8) {
        const int kk0  = k0 + acol;
        const int seg  = kk0 >> 10;
        const int kloc = kk0 & 1023;
        float4 av;
        if (seg == 0) {
            const float4 t = *(const float4*)&g_uvqk[(size_t)m * UVQK_ + kloc];
            av.x = silu_f(t.x); av.y = silu_f(t.y); av.z = silu_f(t.z); av.w = silu_f(t.w);
        } else if (seg == 1) {
            av = *(const float4*)&g_attn[(size_t)m * E_ + kloc];
        } else {
            const float4 t = *(const float4*)&g_uvqk[(size_t)m * UVQK_ + kloc];
            const float4 nn = *(const float4*)&g_nattn[(size_t)m * E_ + kloc];
            av.x = silu_f(t.x) * nn.x;
            av.y = silu_f(t.y) * nn.y;
            av.z = silu_f(t.z) * nn.z;
            av.w = silu_f(t.w) * nn.w;
        }
        As[acol + 0][arow] = av.x;
        As[acol + 1][arow] = av.y;
        As[acol + 2][arow] = av.z;
        As[acol + 3][arow] = av.w;
        *(float4*)&Bs[brow][bcol] = *(const float4*)(Bptr + (size_t)k0 * N);
        __syncthreads();
#pragma unroll
        for (int kk = 0; kk < 8; kk++) {
            const float4 a0 = *(const float4*)&As[kk][ty * 8];
            const float4 a1 = *(const float4*)&As[kk][ty * 8 + 4];
            const float4 b0 = *(const float4*)&Bs[kk][tx * 8];
            const float4 b1 = *(const float4*)&Bs[kk][tx * 8 + 4];
            const float ar[8] = {a0.x, a0.y, a0.z, a0.w, a1.x, a1.y, a1.z, a1.w};
            const float br[8] = {b0.x, b0.y, b0.z, b0.w, b1.x, b1.y, b1.z, b1.w};
#pragma unroll
            for (int i = 0; i < 8; i++)
#pragma unroll
                for (int j = 0; j < 8; j++)
                    acc[i][j] = fmaf(ar[i], br[j], acc[i][j]);
        }
        __syncthreads();
    }

#pragma unroll
    for (int i = 0; i < 8; i++) {
        const int r = row0 + ty * 8 + i;
        const float* xp = x + (size_t)r * N + col0 + tx * 8;
        float* op = out + (size_t)r * N + col0 + tx * 8;
#pragma unroll
        for (int j = 0; j < 8; j += 4) {
            const float4 xv = *(const float4*)(xp + j);
            float4 o;
            o.x = acc[i][j + 0] + xv.x;
            o.y = acc[i][j + 1] + xv.y;
            o.z = acc[i][j + 2] + xv.z;
            o.w = acc[i][j + 3] + xv.w;
            *(float4*)(op + j) = o;
        }
    }
}

// ---------------------------------------------------------------------------
// Launch
// ---------------------------------------------------------------------------
extern "C" void kernel_launch(void* const* d_in, const int* in_sizes, int n_in,
                              void* d_out, int out_size) {
    const float* x        = (const float*)d_in[0];
    const int*   ntg      = (const int*)d_in[1];
    const float* uvqk_w   = (const float*)d_in[2];
    const float* uvqk_b   = (const float*)d_in[3];
    const float* out_w    = (const float*)d_in[4];
    const float* in_scale = (const float*)d_in[5];
    const float* in_bias  = (const float*)d_in[6];
    const float* out_scale= (const float*)d_in[7];
    const float* out_bias = (const float*)d_in[8];
    float* out = (float*)d_out;

    (void)in_sizes; (void)n_in; (void)out_size;

    static bool attr_set = false;
    if (!attr_set) {
        cudaFuncSetAttribute(attn_kernel, cudaFuncAttributeMaxDynamicSharedMemorySize,
                             (int)ATTN_SMEM);
        attr_set = true;
    }

    // 1. LayerNorm(x) -> g_xn
    ln_in_kernel<<<MTOT, 256>>>(x, in_scale, in_bias);

    // 2. g_uvqk = g_xn @ uvqk_w + beta
    gemm_uvqk_kernel<<<dim3(UVQK_ / 128, MTOT / 128), 256>>>(uvqk_w, uvqk_b);

    // 3. silu-attention -> g_attn
    attn_kernel<<<dim3(S_ / 64, H_, B_), 256, ATTN_SMEM>>>(ntg);

    // 4. LayerNorm(attn) -> g_nattn
    ln_attn_kernel<<<MTOT, 256>>>(out_scale, out_bias);

    // 5. out = x + [u, attn, u*nattn] @ out_w
    gemm_out_kernel<<<dim3(E_ / 128, MTOT / 128), 256>>>(out_w, x, out);
}

// round 3
// speedup vs baseline: 1.9388x; 1.9388x over previous
#include <cuda_runtime.h>
#include <math.h>
#include <stdint.h>

// Problem constants
#define B_    4
#define S_    2048
#define E_    1024
#define H_    8
#define D_    128
#define UVQK_ 4096
#define MTOT  (B_ * S_)

#define ALPHA_F 0.08838834764831845f   // 1/sqrt(128)
#define INV_S_F (1.0f / 2048.0f)

// ---------------------------------------------------------------------------
// Scratch
// ---------------------------------------------------------------------------
__device__ float g_xn[(size_t)MTOT * E_];
__device__ float g_uvqk[(size_t)MTOT * UVQK_];
__device__ float g_attn[(size_t)MTOT * E_];
__device__ float g_nattn[(size_t)MTOT * E_];

__device__ __forceinline__ float silu_f(float v) {
    return v / (1.0f + __expf(-v));
}
__device__ __forceinline__ uint32_t f2tf(float f) {
    uint32_t u;
    asm("cvt.rna.tf32.f32 %0, %1;" : "=r"(u) : "f"(f));
    return u;
}
__device__ __forceinline__ void mma8(float* c, const uint32_t* a, const uint32_t* b) {
    asm volatile(
        "mma.sync.aligned.m16n8k8.row.col.f32.tf32.tf32.f32 "
        "{%0,%1,%2,%3}, {%4,%5,%6,%7}, {%8,%9}, {%0,%1,%2,%3};"
        : "+f"(c[0]), "+f"(c[1]), "+f"(c[2]), "+f"(c[3])
        : "r"(a[0]), "r"(a[1]), "r"(a[2]), "r"(a[3]), "r"(b[0]), "r"(b[1]));
}
__device__ __forceinline__ uint4 cvt4(float4 v) {
    uint4 u;
    u.x = f2tf(v.x); u.y = f2tf(v.y); u.z = f2tf(v.z); u.w = f2tf(v.w);
    return u;
}

// ---------------------------------------------------------------------------
// LayerNorm (unchanged, memory-bound)
// ---------------------------------------------------------------------------
__device__ __forceinline__ void ln_row(const float* __restrict__ in,
                                       const float* __restrict__ sc,
                                       const float* __restrict__ bi,
                                       float* __restrict__ out) {
    __shared__ float red[16];
    const size_t row = blockIdx.x;
    const int tid = threadIdx.x;
    const float4 v = ((const float4*)(in + row * E_))[tid];

    float s  = v.x + v.y + v.z + v.w;
    float sq = v.x * v.x + v.y * v.y + v.z * v.z + v.w * v.w;
#pragma unroll
    for (int o = 16; o > 0; o >>= 1) {
        s  += __shfl_xor_sync(0xFFFFFFFFu, s, o);
        sq += __shfl_xor_sync(0xFFFFFFFFu, sq, o);
    }
    const int warp = tid >> 5, lane = tid & 31;
    if (lane == 0) { red[warp] = s; red[8 + warp] = sq; }
    __syncthreads();
    if (tid < 32) {
        float ss = (lane < 8) ? red[lane] : 0.0f;
        float qq = (lane < 8) ? red[8 + lane] : 0.0f;
#pragma unroll
        for (int o = 4; o > 0; o >>= 1) {
            ss += __shfl_xor_sync(0xFFFFFFFFu, ss, o);
            qq += __shfl_xor_sync(0xFFFFFFFFu, qq, o);
        }
        if (lane == 0) { red[0] = ss; red[1] = qq; }
    }
    __syncthreads();
    const float mean = red[0] * (1.0f / (float)E_);
    const float var  = red[1] * (1.0f / (float)E_) - mean * mean;
    const float r    = rsqrtf(var + 1e-6f);

    const float4 scv = ((const float4*)sc)[tid];
    const float4 biv = ((const float4*)bi)[tid];
    float4 o;
    o.x = (v.x - mean) * r * scv.x + biv.x;
    o.y = (v.y - mean) * r * scv.y + biv.y;
    o.z = (v.z - mean) * r * scv.z + biv.z;
    o.w = (v.w - mean) * r * scv.w + biv.w;
    ((float4*)(out + row * E_))[tid] = o;
}

__global__ __launch_bounds__(256) void ln_in_kernel(const float* __restrict__ x,
                                                    const float* __restrict__ sc,
                                                    const float* __restrict__ bi) {
    ln_row(x, sc, bi, g_xn);
}
__global__ __launch_bounds__(256) void ln_attn_kernel(const float* __restrict__ sc,
                                                      const float* __restrict__ bi) {
    ln_row(g_attn, sc, bi, g_nattn);
}

// ---------------------------------------------------------------------------
// Tensor-core GEMM common geometry:
//   128x128 tile, BK=16, 128 threads (4 warps 2x2), warp tile 64x64
//   As[m][20]  (stride 20 % 32 == 4 -> frag loads conflict-free)
//   Bs[k][136] (stride 136 % 32 == 8 -> frag loads conflict-free)
// ---------------------------------------------------------------------------
#define APAD 20
#define BPAD 136

// GEMM1: g_uvqk[8192,4096] = g_xn[8192,1024] @ W[1024,4096] + beta
__global__ __launch_bounds__(128) void gemm_uvqk_tc(const float* __restrict__ W,
                                                    const float* __restrict__ beta) {
    constexpr int K = E_, N = UVQK_;
    __shared__ __align__(16) uint32_t As[128 * APAD];
    __shared__ __align__(16) uint32_t Bs[16 * BPAD];

    const int tid = threadIdx.x;
    const int row0 = blockIdx.y * 128, col0 = blockIdx.x * 128;
    const int wid = tid >> 5, lane = tid & 31;
    const int g = lane >> 2, tg = lane & 3;
    const int wm = wid >> 1, wn = wid & 1;
    const int r0 = tid >> 2, q = tid & 3;   // A loader
    const int c4 = lane;                    // B loader col-quad

    float acc[4][8][4];
#pragma unroll
    for (int i = 0; i < 4; i++)
#pragma unroll
        for (int j = 0; j < 8; j++)
#pragma unroll
            for (int r = 0; r < 4; r++) acc[i][j][r] = 0.0f;

    float4 ra[4], rb[4];
#pragma unroll
    for (int p = 0; p < 4; p++) {
        ra[p] = *(const float4*)&g_xn[(size_t)(row0 + r0 + 32 * p) * K + q * 4];
        rb[p] = *(const float4*)&W[(size_t)(wid + 4 * p) * N + col0 + c4 * 4];
    }

    for (int k0 = 0; k0 < K; k0 += 16) {
        __syncthreads();
#pragma unroll
        for (int p = 0; p < 4; p++) {
            *(uint4*)&As[(r0 + 32 * p) * APAD + q * 4] = cvt4(ra[p]);
            *(uint4*)&Bs[(wid + 4 * p) * BPAD + c4 * 4] = cvt4(rb[p]);
        }
        __syncthreads();
        if (k0 + 16 < K) {
#pragma unroll
            for (int p = 0; p < 4; p++) {
                ra[p] = *(const float4*)&g_xn[(size_t)(row0 + r0 + 32 * p) * K + k0 + 16 + q * 4];
                rb[p] = *(const float4*)&W[(size_t)(k0 + 16 + wid + 4 * p) * N + col0 + c4 * 4];
            }
        }
#pragma unroll
        for (int kc = 0; kc < 16; kc += 8) {
            uint32_t a[4][4], b[8][2];
#pragma unroll
            for (int mi = 0; mi < 4; mi++) {
                const int ab = (wm * 64 + mi * 16 + g) * APAD + kc + tg;
                a[mi][0] = As[ab];
                a[mi][1] = As[ab + 8 * APAD];
                a[mi][2] = As[ab + 4];
                a[mi][3] = As[ab + 8 * APAD + 4];
            }
#pragma unroll
            for (int ni = 0; ni < 8; ni++) {
                const int bb = (kc + tg) * BPAD + wn * 64 + ni * 8 + g;
                b[ni][0] = Bs[bb];
                b[ni][1] = Bs[bb + 4 * BPAD];
            }
#pragma unroll
            for (int mi = 0; mi < 4; mi++)
#pragma unroll
                for (int ni = 0; ni < 8; ni++)
                    mma8(acc[mi][ni], a[mi], b[ni]);
        }
    }

#pragma unroll
    for (int mi = 0; mi < 4; mi++) {
        const int r1 = row0 + wm * 64 + mi * 16 + g;
#pragma unroll
        for (int ni = 0; ni < 8; ni++) {
            const int c = col0 + wn * 64 + ni * 8 + 2 * tg;
            const float2 bb = *(const float2*)&beta[c];
            float2 o0 = {acc[mi][ni][0] + bb.x, acc[mi][ni][1] + bb.y};
            float2 o1 = {acc[mi][ni][2] + bb.x, acc[mi][ni][3] + bb.y};
            *(float2*)&g_uvqk[(size_t)r1 * N + c] = o0;
            *(float2*)&g_uvqk[(size_t)(r1 + 8) * N + c] = o1;
        }
    }
}

// GEMM2: out[8192,1024] = x + A[8192,3072] @ W2[3072,1024]
__global__ __launch_bounds__(128) void gemm_out_tc(const float* __restrict__ W2,
                                                   const float* __restrict__ x,
                                                   float* __restrict__ out) {
    constexpr int K = 3072, N = E_;
    __shared__ __align__(16) uint32_t As[128 * APAD];
    __shared__ __align__(16) uint32_t Bs[16 * BPAD];

    const int tid = threadIdx.x;
    const int row0 = blockIdx.y * 128, col0 = blockIdx.x * 128;
    const int wid = tid >> 5, lane = tid & 31;
    const int g = lane >> 2, tg = lane & 3;
    const int wm = wid >> 1, wn = wid & 1;
    const int r0 = tid >> 2, q = tid & 3;
    const int c4 = lane;

    float acc[4][8][4];
#pragma unroll
    for (int i = 0; i < 4; i++)
#pragma unroll
        for (int j = 0; j < 8; j++)
#pragma unroll
            for (int r = 0; r < 4; r++) acc[i][j][r] = 0.0f;

    float4 ra[4], rb[4];

    auto loadA = [&](int k0, int p) -> float4 {
        const int m = row0 + r0 + 32 * p;
        const int kg = k0 + q * 4;
        const int seg = kg >> 10, kloc = kg & 1023;
        float4 av;
        if (seg == 0) {
            const float4 t = *(const float4*)&g_uvqk[(size_t)m * UVQK_ + kloc];
            av.x = silu_f(t.x); av.y = silu_f(t.y); av.z = silu_f(t.z); av.w = silu_f(t.w);
        } else if (seg == 1) {
            av = *(const float4*)&g_attn[(size_t)m * E_ + kloc];
        } else {
            const float4 t = *(const float4*)&g_uvqk[(size_t)m * UVQK_ + kloc];
            const float4 nn = *(const float4*)&g_nattn[(size_t)m * E_ + kloc];
            av.x = silu_f(t.x) * nn.x;
            av.y = silu_f(t.y) * nn.y;
            av.z = silu_f(t.z) * nn.z;
            av.w = silu_f(t.w) * nn.w;
        }
        return av;
    };

#pragma unroll
    for (int p = 0; p < 4; p++) {
        ra[p] = loadA(0, p);
        rb[p] = *(const float4*)&W2[(size_t)(wid + 4 * p) * N + col0 + c4 * 4];
    }

    for (int k0 = 0; k0 < K; k0 += 16) {
        __syncthreads();
#pragma unroll
        for (int p = 0; p < 4; p++) {
            *(uint4*)&As[(r0 + 32 * p) * APAD + q * 4] = cvt4(ra[p]);
            *(uint4*)&Bs[(wid + 4 * p) * BPAD + c4 * 4] = cvt4(rb[p]);
        }
        __syncthreads();
        if (k0 + 16 < K) {
#pragma unroll
            for (int p = 0; p < 4; p++) {
                ra[p] = loadA(k0 + 16, p);
                rb[p] = *(const float4*)&W2[(size_t)(k0 + 16 + wid + 4 * p) * N + col0 + c4 * 4];
            }
        }
#pragma unroll
        for (int kc = 0; kc < 16; kc += 8) {
            uint32_t a[4][4], b[8][2];
#pragma unroll
            for (int mi = 0; mi < 4; mi++) {
                const int ab = (wm * 64 + mi * 16 + g) * APAD + kc + tg;
                a[mi][0] = As[ab];
                a[mi][1] = As[ab + 8 * APAD];
                a[mi][2] = As[ab + 4];
                a[mi][3] = As[ab + 8 * APAD + 4];
            }
#pragma unroll
            for (int ni = 0; ni < 8; ni++) {
                const int bb = (kc + tg) * BPAD + wn * 64 + ni * 8 + g;
                b[ni][0] = Bs[bb];
                b[ni][1] = Bs[bb + 4 * BPAD];
            }
#pragma unroll
            for (int mi = 0; mi < 4; mi++)
#pragma unroll
                for (int ni = 0; ni < 8; ni++)
                    mma8(acc[mi][ni], a[mi], b[ni]);
        }
    }

#pragma unroll
    for (int mi = 0; mi < 4; mi++) {
        const int r1 = row0 + wm * 64 + mi * 16 + g;
#pragma unroll
        for (int ni = 0; ni < 8; ni++) {
            const int c = col0 + wn * 64 + ni * 8 + 2 * tg;
            const float2 x0 = *(const float2*)&x[(size_t)r1 * N + c];
            const float2 x1 = *(const float2*)&x[(size_t)(r1 + 8) * N + c];
            float2 o0 = {acc[mi][ni][0] + x0.x, acc[mi][ni][1] + x0.y};
            float2 o1 = {acc[mi][ni][2] + x1.x, acc[mi][ni][3] + x1.y};
            *(float2*)&out[(size_t)r1 * N + c] = o0;
            *(float2*)&out[(size_t)(r1 + 8) * N + c] = o1;
        }
    }
}

// ---------------------------------------------------------------------------
// Attention with tensor cores.
// CTA: 128 threads (4 warps 2x2), one 64-row q-tile per (b,h).
// Stage1: S = Q @ K^T   (Q [q][d] stride 132, K [kv][d] stride 132)
// Stage2: O += P @ V    (P [q][kv] stride 68, V [kv][d] stride 136)
// ---------------------------------------------------------------------------
#define QPAD 132
#define VPAD 136
#define PPAD 68
#define ATTN_SMEM_WORDS (64 * QPAD + 64 * QPAD + 64 * VPAD + 64 * PPAD)
#define ATTN_SMEM_BYTES (ATTN_SMEM_WORDS * 4)

__global__ __launch_bounds__(128) void attn_tc(const int* __restrict__ num_targets) {
    extern __shared__ uint32_t smw[];
    uint32_t* qs = smw;
    uint32_t* ks = qs + 64 * QPAD;
    uint32_t* vs = ks + 64 * QPAD;
    uint32_t* ps = vs + 64 * VPAD;

    const int tid = threadIdx.x;
    const int wid = tid >> 5, lane = tid & 31;
    const int g = lane >> 2, tg = lane & 3;
    const int wm = wid >> 1, wn = wid & 1;
    const int c4 = lane;

    const int b = blockIdx.z, h = blockIdx.y, qt = blockIdx.x;
    const int q0 = qt * 64;
    const int limit = S_ - num_targets[b];
    const float* base = g_uvqk + (size_t)b * S_ * UVQK_;

    // Load Q tile (64 x 128) once
#pragma unroll 4
    for (int p = 0; p < 16; p++) {
        const int row = wid + 4 * p;
        const float4 v = *(const float4*)&base[(size_t)(q0 + row) * UVQK_ + 2048 + h * D_ + c4 * 4];
        *(uint4*)&qs[row * QPAD + c4 * 4] = cvt4(v);
    }

    float oacc[2][8][4];
#pragma unroll
    for (int i = 0; i < 2; i++)
#pragma unroll
        for (int j = 0; j < 8; j++)
#pragma unroll
            for (int r = 0; r < 4; r++) oacc[i][j][r] = 0.0f;

    for (int t = 0; t <= qt; t++) {
        const int k0 = t * 64;
        __syncthreads();
#pragma unroll 4
        for (int p = 0; p < 16; p++) {
            const int row = wid + 4 * p;
            const float* rb = &base[(size_t)(k0 + row) * UVQK_ + h * D_ + c4 * 4];
            *(uint4*)&ks[row * QPAD + c4 * 4] = cvt4(*(const float4*)(rb + 3072));
            *(uint4*)&vs[row * VPAD + c4 * 4] = cvt4(*(const float4*)(rb + 1024));
        }
        __syncthreads();

        // ----- Stage 1: S = Q @ K^T  (warp tile 32x32) -----
        float sacc[2][4][4];
#pragma unroll
        for (int i = 0; i < 2; i++)
#pragma unroll
            for (int j = 0; j < 4; j++)
#pragma unroll
                for (int r = 0; r < 4; r++) sacc[i][j][r] = 0.0f;

#pragma unroll
        for (int kc = 0; kc < D_; kc += 8) {
            uint32_t a[2][4], bf[4][2];
#pragma unroll
            for (int mi = 0; mi < 2; mi++) {
                const int ab = (wm * 32 + mi * 16 + g) * QPAD + kc + tg;
                a[mi][0] = qs[ab];
                a[mi][1] = qs[ab + 8 * QPAD];
                a[mi][2] = qs[ab + 4];
                a[mi][3] = qs[ab + 8 * QPAD + 4];
            }
#pragma unroll
            for (int ni = 0; ni < 4; ni++) {
                const int bb = (wn * 32 + ni * 8 + g) * QPAD + kc + tg;
                bf[ni][0] = ks[bb];
                bf[ni][1] = ks[bb + 4];
            }
#pragma unroll
            for (int mi = 0; mi < 2; mi++)
#pragma unroll
                for (int ni = 0; ni < 4; ni++)
                    mma8(sacc[mi][ni], a[mi], bf[ni]);
        }

        // silu + mask + store P (tf32) to smem
#pragma unroll
        for (int mi = 0; mi < 2; mi++) {
            const int qr = wm * 32 + mi * 16 + g;
            const int qg0 = q0 + qr, qg1 = qg0 + 8;
            const int iq0 = min(qg0, limit), iq1 = min(qg1, limit);
#pragma unroll
            for (int ni = 0; ni < 4; ni++) {
                const int cc = wn * 32 + ni * 8 + 2 * tg;
                const int kg0 = k0 + cc, kg1 = kg0 + 1;
                const int ik0 = min(kg0, limit), ik1 = min(kg1, limit);

                float p00 = ((qg0 == kg0) || (iq0 > ik0)) ? silu_f(sacc[mi][ni][0] * ALPHA_F) * INV_S_F : 0.0f;
                float p01 = ((qg0 == kg1) || (iq0 > ik1)) ? silu_f(sacc[mi][ni][1] * ALPHA_F) * INV_S_F : 0.0f;
                float p10 = ((qg1 == kg0) || (iq1 > ik0)) ? silu_f(sacc[mi][ni][2] * ALPHA_F) * INV_S_F : 0.0f;
                float p11 = ((qg1 == kg1) || (iq1 > ik1)) ? silu_f(sacc[mi][ni][3] * ALPHA_F) * INV_S_F : 0.0f;

                uint2 u0 = {f2tf(p00), f2tf(p01)};
                uint2 u1 = {f2tf(p10), f2tf(p11)};
                *(uint2*)&ps[qr * PPAD + cc] = u0;
                *(uint2*)&ps[(qr + 8) * PPAD + cc] = u1;
            }
        }
        __syncthreads();

        // ----- Stage 2: O += P @ V  (warp tile 32x64) -----
#pragma unroll
        for (int kc = 0; kc < 64; kc += 8) {
            uint32_t a[2][4], bf[8][2];
#pragma unroll
            for (int mi = 0; mi < 2; mi++) {
                const int ab = (wm * 32 + mi * 16 + g) * PPAD + kc + tg;
                a[mi][0] = ps[ab];
                a[mi][1] = ps[ab + 8 * PPAD];
                a[mi][2] = ps[ab + 4];
                a[mi][3] = ps[ab + 8 * PPAD + 4];
            }
#pragma unroll
            for (int ni = 0; ni < 8; ni++) {
                const int bb = (kc + tg) * VPAD + wn * 64 + ni * 8 + g;
                bf[ni][0] = vs[bb];
                bf[ni][1] = vs[bb + 4 * VPAD];
            }
#pragma unroll
            for (int mi = 0; mi < 2; mi++)
#pragma unroll
                for (int ni = 0; ni < 8; ni++)
                    mma8(oacc[mi][ni], a[mi], bf[ni]);
        }
    }

    // Epilogue: write attn output (B*S, H*D)
#pragma unroll
    for (int mi = 0; mi < 2; mi++) {
        const int r1 = q0 + wm * 32 + mi * 16 + g;
#pragma unroll
        for (int ni = 0; ni < 8; ni++) {
            const int c = h * D_ + wn * 64 + ni * 8 + 2 * tg;
            float2 o0 = {oacc[mi][ni][0], oacc[mi][ni][1]};
            float2 o1 = {oacc[mi][ni][2], oacc[mi][ni][3]};
            *(float2*)&g_attn[(size_t)(b * S_ + r1) * E_ + c] = o0;
            *(float2*)&g_attn[(size_t)(b * S_ + r1 + 8) * E_ + c] = o1;
        }
    }
}

// ---------------------------------------------------------------------------
// Launch
// ---------------------------------------------------------------------------
extern "C" void kernel_launch(void* const* d_in, const int* in_sizes, int n_in,
                              void* d_out, int out_size) {
    const float* x        = (const float*)d_in[0];
    const int*   ntg      = (const int*)d_in[1];
    const float* uvqk_w   = (const float*)d_in[2];
    const float* uvqk_b   = (const float*)d_in[3];
    const float* out_w    = (const float*)d_in[4];
    const float* in_scale = (const float*)d_in[5];
    const float* in_bias  = (const float*)d_in[6];
    const float* out_scale= (const float*)d_in[7];
    const float* out_bias = (const float*)d_in[8];
    float* out = (float*)d_out;

    (void)in_sizes; (void)n_in; (void)out_size;

    static bool attr_set = false;
    if (!attr_set) {
        cudaFuncSetAttribute(attn_tc, cudaFuncAttributeMaxDynamicSharedMemorySize,
                             ATTN_SMEM_BYTES);
        attr_set = true;
    }

    ln_in_kernel<<<MTOT, 256>>>(x, in_scale, in_bias);
    gemm_uvqk_tc<<<dim3(UVQK_ / 128, MTOT / 128), 128>>>(uvqk_w, uvqk_b);
    attn_tc<<<dim3(S_ / 64, H_, B_), 128, ATTN_SMEM_BYTES>>>(ntg);
    ln_attn_kernel<<<MTOT, 256>>>(out_scale, out_bias);
    gemm_out_tc<<<dim3(E_ / 128, MTOT / 128), 128>>>(out_w, x, out);
}

// round 4
// speedup vs baseline: 2.7779x; 1.4328x over previous
#include <cuda_runtime.h>
#include <math.h>
#include <stdint.h>

// Problem constants
#define B_    4
#define S_    2048
#define E_    1024
#define H_    8
#define D_    128
#define UVQK_ 4096
#define MTOT  (B_ * S_)

#define ALPHA_F 0.08838834764831845f   // 1/sqrt(128)
#define INV_S_F (1.0f / 2048.0f)

// ---------------------------------------------------------------------------
// Scratch
// ---------------------------------------------------------------------------
__device__ float g_xn[(size_t)MTOT * E_];
__device__ float g_uvqk[(size_t)MTOT * UVQK_];
__device__ float g_attn[(size_t)MTOT * E_];
__device__ float g_nattn[(size_t)MTOT * E_];

__device__ __forceinline__ float silu_f(float v) {
    return v / (1.0f + __expf(-v));
}
__device__ __forceinline__ void mma8(float* c, const uint32_t* a, const uint32_t* b) {
    asm volatile(
        "mma.sync.aligned.m16n8k8.row.col.f32.tf32.tf32.f32 "
        "{%0,%1,%2,%3}, {%4,%5,%6,%7}, {%8,%9}, {%0,%1,%2,%3};"
        : "+f"(c[0]), "+f"(c[1]), "+f"(c[2]), "+f"(c[3])
        : "r"(a[0]), "r"(a[1]), "r"(a[2]), "r"(a[3]), "r"(b[0]), "r"(b[1]));
}
__device__ __forceinline__ uint32_t s2u(const void* p) {
    return (uint32_t)__cvta_generic_to_shared(p);
}
__device__ __forceinline__ void cpa16(uint32_t dst, const void* src) {
    asm volatile("cp.async.cg.shared.global [%0], [%1], 16;" :: "r"(dst), "l"(src));
}
#define CP_COMMIT() asm volatile("cp.async.commit_group;")
#define CP_WAIT(N)  asm volatile("cp.async.wait_group %0;" :: "n"(N))

// ---------------------------------------------------------------------------
// LayerNorm (memory-bound, unchanged)
// ---------------------------------------------------------------------------
__device__ __forceinline__ void ln_row(const float* __restrict__ in,
                                       const float* __restrict__ sc,
                                       const float* __restrict__ bi,
                                       float* __restrict__ out) {
    __shared__ float red[16];
    const size_t row = blockIdx.x;
    const int tid = threadIdx.x;
    const float4 v = ((const float4*)(in + row * E_))[tid];

    float s  = v.x + v.y + v.z + v.w;
    float sq = v.x * v.x + v.y * v.y + v.z * v.z + v.w * v.w;
#pragma unroll
    for (int o = 16; o > 0; o >>= 1) {
        s  += __shfl_xor_sync(0xFFFFFFFFu, s, o);
        sq += __shfl_xor_sync(0xFFFFFFFFu, sq, o);
    }
    const int warp = tid >> 5, lane = tid & 31;
    if (lane == 0) { red[warp] = s; red[8 + warp] = sq; }
    __syncthreads();
    if (tid < 32) {
        float ss = (lane < 8) ? red[lane] : 0.0f;
        float qq = (lane < 8) ? red[8 + lane] : 0.0f;
#pragma unroll
        for (int o = 4; o > 0; o >>= 1) {
            ss += __shfl_xor_sync(0xFFFFFFFFu, ss, o);
            qq += __shfl_xor_sync(0xFFFFFFFFu, qq, o);
        }
        if (lane == 0) { red[0] = ss; red[1] = qq; }
    }
    __syncthreads();
    const float mean = red[0] * (1.0f / (float)E_);
    const float var  = red[1] * (1.0f / (float)E_) - mean * mean;
    const float r    = rsqrtf(var + 1e-6f);

    const float4 scv = ((const float4*)sc)[tid];
    const float4 biv = ((const float4*)bi)[tid];
    float4 o;
    o.x = (v.x - mean) * r * scv.x + biv.x;
    o.y = (v.y - mean) * r * scv.y + biv.y;
    o.z = (v.z - mean) * r * scv.z + biv.z;
    o.w = (v.w - mean) * r * scv.w + biv.w;
    ((float4*)(out + row * E_))[tid] = o;
}

__global__ __launch_bounds__(256) void ln_in_kernel(const float* __restrict__ x,
                                                    const float* __restrict__ sc,
                                                    const float* __restrict__ bi) {
    ln_row(x, sc, bi, g_xn);
}
__global__ __launch_bounds__(256) void ln_attn_kernel(const float* __restrict__ sc,
                                                      const float* __restrict__ bi) {
    ln_row(g_attn, sc, bi, g_nattn);
}

// ---------------------------------------------------------------------------
// GEMM geometry: 128x128 tile, BK=16, 256 threads (8 warps, 2x4 grid),
// warp tile 64x32. Double-buffered smem.
//   As[m][20]  (stride 20 % 32 == 4 -> conflict-free fragment loads)
//   Bs[k][136] (stride 136 % 32 == 8 -> conflict-free fragment loads)
// ---------------------------------------------------------------------------
#define APAD 20
#define BPAD 136
#define ASTG (128 * APAD)
#define BSTG (16 * BPAD)

// GEMM1: g_uvqk[8192,4096] = g_xn[8192,1024] @ W[1024,4096] + beta
__global__ __launch_bounds__(256) void gemm_uvqk_tc(const float* __restrict__ W,
                                                    const float* __restrict__ beta) {
    constexpr int K = E_, N = UVQK_;
    __shared__ __align__(16) uint32_t As[2 * ASTG];
    __shared__ __align__(16) uint32_t Bs[2 * BSTG];

    const int tid = threadIdx.x;
    const int row0 = blockIdx.y * 128, col0 = blockIdx.x * 128;
    const int wid = tid >> 5, lane = tid & 31;
    const int g = lane >> 2, tg = lane & 3;
    const int wm = wid >> 2, wn = wid & 3;
    const uint32_t asb = s2u(As), bsb = s2u(Bs);

    auto docopy = [&](int k0, int buf) {
#pragma unroll
        for (int p = 0; p < 2; p++) {
            const int id = tid + 256 * p;
            const int r = id >> 2, q = id & 3;
            cpa16(asb + (buf * ASTG + r * APAD + q * 4) * 4,
                  &g_xn[(size_t)(row0 + r) * K + k0 + q * 4]);
        }
#pragma unroll
        for (int p = 0; p < 2; p++) {
            const int id = tid + 256 * p;
            const int r = id >> 5, c = id & 31;
            cpa16(bsb + (buf * BSTG + r * BPAD + c * 4) * 4,
                  &W[(size_t)(k0 + r) * N + col0 + c * 4]);
        }
    };

    float acc[4][4][4];
#pragma unroll
    for (int i = 0; i < 4; i++)
#pragma unroll
        for (int j = 0; j < 4; j++)
#pragma unroll
            for (int r = 0; r < 4; r++) acc[i][j][r] = 0.0f;

    docopy(0, 0); CP_COMMIT();
    docopy(16, 1); CP_COMMIT();

    for (int k0 = 0; k0 < K; k0 += 16) {
        const int buf = (k0 >> 4) & 1;
        CP_WAIT(1);
        __syncthreads();
#pragma unroll
        for (int kc = 0; kc < 16; kc += 8) {
            uint32_t a[4][4], b[4][2];
#pragma unroll
            for (int mi = 0; mi < 4; mi++) {
                const int ab = buf * ASTG + (wm * 64 + mi * 16 + g) * APAD + kc + tg;
                a[mi][0] = As[ab];
                a[mi][1] = As[ab + 8 * APAD];
                a[mi][2] = As[ab + 4];
                a[mi][3] = As[ab + 8 * APAD + 4];
            }
#pragma unroll
            for (int ni = 0; ni < 4; ni++) {
                const int bb = buf * BSTG + (kc + tg) * BPAD + wn * 32 + ni * 8 + g;
                b[ni][0] = Bs[bb];
                b[ni][1] = Bs[bb + 4 * BPAD];
            }
#pragma unroll
            for (int mi = 0; mi < 4; mi++)
#pragma unroll
                for (int ni = 0; ni < 4; ni++)
                    mma8(acc[mi][ni], a[mi], b[ni]);
        }
        __syncthreads();
        if (k0 + 32 < K) docopy(k0 + 32, buf);
        CP_COMMIT();
    }

#pragma unroll
    for (int mi = 0; mi < 4; mi++) {
        const int r1 = row0 + wm * 64 + mi * 16 + g;
#pragma unroll
        for (int ni = 0; ni < 4; ni++) {
            const int c = col0 + wn * 32 + ni * 8 + 2 * tg;
            const float2 bb = *(const float2*)&beta[c];
            float2 o0 = {acc[mi][ni][0] + bb.x, acc[mi][ni][1] + bb.y};
            float2 o1 = {acc[mi][ni][2] + bb.x, acc[mi][ni][3] + bb.y};
            *(float2*)&g_uvqk[(size_t)r1 * N + c] = o0;
            *(float2*)&g_uvqk[(size_t)(r1 + 8) * N + c] = o1;
        }
    }
}

// GEMM2: out[8192,1024] = x + A[8192,3072] @ W2[3072,1024]
// A assembled in registers (silu / gating), B via cp.async.
__global__ __launch_bounds__(256) void gemm_out_tc(const float* __restrict__ W2,
                                                   const float* __restrict__ x,
                                                   float* __restrict__ out) {
    constexpr int K = 3072, N = E_;
    __shared__ __align__(16) float As[2 * ASTG];
    __shared__ __align__(16) uint32_t Bs[2 * BSTG];

    const int tid = threadIdx.x;
    const int row0 = blockIdx.y * 128, col0 = blockIdx.x * 128;
    const int wid = tid >> 5, lane = tid & 31;
    const int g = lane >> 2, tg = lane & 3;
    const int wm = wid >> 2, wn = wid & 3;
    const uint32_t bsb = s2u(Bs);
    const uint32_t* Asw = (const uint32_t*)As;

    auto copyB = [&](int k0, int buf) {
#pragma unroll
        for (int p = 0; p < 2; p++) {
            const int id = tid + 256 * p;
            const int r = id >> 5, c = id & 31;
            cpa16(bsb + (buf * BSTG + r * BPAD + c * 4) * 4,
                  &W2[(size_t)(k0 + r) * N + col0 + c * 4]);
        }
    };
    auto loadA = [&](int k0, int p) -> float4 {
        const int id = tid + 256 * p;
        const int r = id >> 2, q = id & 3;
        const int m = row0 + r;
        const int kg = k0 + q * 4;
        const int seg = kg >> 10, kloc = kg & 1023;
        float4 av;
        if (seg == 0) {
            const float4 t = *(const float4*)&g_uvqk[(size_t)m * UVQK_ + kloc];
            av.x = silu_f(t.x); av.y = silu_f(t.y); av.z = silu_f(t.z); av.w = silu_f(t.w);
        } else if (seg == 1) {
            av = *(const float4*)&g_attn[(size_t)m * E_ + kloc];
        } else {
            const float4 t = *(const float4*)&g_uvqk[(size_t)m * UVQK_ + kloc];
            const float4 nn = *(const float4*)&g_nattn[(size_t)m * E_ + kloc];
            av.x = silu_f(t.x) * nn.x;
            av.y = silu_f(t.y) * nn.y;
            av.z = silu_f(t.z) * nn.z;
            av.w = silu_f(t.w) * nn.w;
        }
        return av;
    };

    float acc[4][4][4];
#pragma unroll
    for (int i = 0; i < 4; i++)
#pragma unroll
        for (int j = 0; j < 4; j++)
#pragma unroll
            for (int r = 0; r < 4; r++) acc[i][j][r] = 0.0f;

    float4 ra[2];
#pragma unroll
    for (int p = 0; p < 2; p++) ra[p] = loadA(0, p);
    copyB(0, 0); CP_COMMIT();
    copyB(16, 1); CP_COMMIT();

    for (int k0 = 0; k0 < K; k0 += 16) {
        const int buf = (k0 >> 4) & 1;
        // stage A registers into smem
#pragma unroll
        for (int p = 0; p < 2; p++) {
            const int id = tid + 256 * p;
            const int r = id >> 2, q = id & 3;
            *(float4*)&As[buf * ASTG + r * APAD + q * 4] = ra[p];
        }
        if (k0 + 16 < K) {
#pragma unroll
            for (int p = 0; p < 2; p++) ra[p] = loadA(k0 + 16, p);
        }
        CP_WAIT(1);
        __syncthreads();
#pragma unroll
        for (int kc = 0; kc < 16; kc += 8) {
            uint32_t a[4][4], b[4][2];
#pragma unroll
            for (int mi = 0; mi < 4; mi++) {
                const int ab = buf * ASTG + (wm * 64 + mi * 16 + g) * APAD + kc + tg;
                a[mi][0] = Asw[ab];
                a[mi][1] = Asw[ab + 8 * APAD];
                a[mi][2] = Asw[ab + 4];
                a[mi][3] = Asw[ab + 8 * APAD + 4];
            }
#pragma unroll
            for (int ni = 0; ni < 4; ni++) {
                const int bb = buf * BSTG + (kc + tg) * BPAD + wn * 32 + ni * 8 + g;
                b[ni][0] = Bs[bb];
                b[ni][1] = Bs[bb + 4 * BPAD];
            }
#pragma unroll
            for (int mi = 0; mi < 4; mi++)
#pragma unroll
                for (int ni = 0; ni < 4; ni++)
                    mma8(acc[mi][ni], a[mi], b[ni]);
        }
        __syncthreads();
        if (k0 + 32 < K) copyB(k0 + 32, buf);
        CP_COMMIT();
    }

#pragma unroll
    for (int mi = 0; mi < 4; mi++) {
        const int r1 = row0 + wm * 64 + mi * 16 + g;
#pragma unroll
        for (int ni = 0; ni < 4; ni++) {
            const int c = col0 + wn * 32 + ni * 8 + 2 * tg;
            const float2 x0 = *(const float2*)&x[(size_t)r1 * N + c];
            const float2 x1 = *(const float2*)&x[(size_t)(r1 + 8) * N + c];
            float2 o0 = {acc[mi][ni][0] + x0.x, acc[mi][ni][1] + x0.y};
            float2 o1 = {acc[mi][ni][2] + x1.x, acc[mi][ni][3] + x1.y};
            *(float2*)&out[(size_t)r1 * N + c] = o0;
            *(float2*)&out[(size_t)(r1 + 8) * N + c] = o1;
        }
    }
}

// ---------------------------------------------------------------------------
// Attention, tensor cores, 256 threads (8 warps, 4x2), 128 q-rows per CTA.
// Stage1: S[128,64] = Q @ K^T  (warp tile 32x32)
// Stage2: O[128,128] += P @ V  (warp tile 32x64)
// Reversed tile order: heaviest causal tiles scheduled first.
// ---------------------------------------------------------------------------
#define QPAD 132
#define VPAD 136
#define PPAD 68
#define ATTN_SMEM_WORDS (128 * QPAD + 64 * QPAD + 64 * VPAD + 128 * PPAD)
#define ATTN_SMEM_BYTES (ATTN_SMEM_WORDS * 4)

__global__ __launch_bounds__(256) void attn_tc(const int* __restrict__ num_targets) {
    extern __shared__ uint32_t smw[];
    uint32_t* qs = smw;                    // 128 x QPAD
    uint32_t* ks = qs + 128 * QPAD;        // 64 x QPAD
    uint32_t* vs = ks + 64 * QPAD;         // 64 x VPAD
    float*    ps = (float*)(vs + 64 * VPAD);  // 128 x PPAD

    const int tid = threadIdx.x;
    const int wid = tid >> 5, lane = tid & 31;
    const int g = lane >> 2, tg = lane & 3;
    const int wm = wid >> 1, wn = wid & 1;

    const int b = blockIdx.z, h = blockIdx.y;
    const int qt = (gridDim.x - 1) - blockIdx.x;   // reversed: big tiles first
    const int q0 = qt * 128;
    const int limit = S_ - num_targets[b];
    const float* base = g_uvqk + (size_t)b * S_ * UVQK_;

    const uint32_t qsb = s2u(qs), ksb = s2u(ks), vsb = s2u(vs);

    // Q tile (128 x 128) via cp.async, group 0
#pragma unroll
    for (int p = 0; p < 16; p++) {
        const int id = tid + 256 * p;
        const int r = id >> 5, c = id & 31;
        cpa16(qsb + (r * QPAD + c * 4) * 4,
              &base[(size_t)(q0 + r) * UVQK_ + 2048 + h * D_ + c * 4]);
    }
    CP_COMMIT();

    float oacc[2][8][4];
#pragma unroll
    for (int i = 0; i < 2; i++)
#pragma unroll
        for (int j = 0; j < 8; j++)
#pragma unroll
            for (int r = 0; r < 4; r++) oacc[i][j][r] = 0.0f;

    const int ntile = 2 * qt + 2;
    for (int t = 0; t < ntile; t++) {
        const int k0 = t * 64;
        __syncthreads();   // previous compute done with ks/vs
#pragma unroll
        for (int p = 0; p < 8; p++) {
            const int id = tid + 256 * p;
            const int r = id >> 5, c = id & 31;
            const float* rb = &base[(size_t)(k0 + r) * UVQK_ + h * D_ + c * 4];
            cpa16(ksb + (r * QPAD + c * 4) * 4, rb + 3072);
            cpa16(vsb + (r * VPAD + c * 4) * 4, rb + 1024);
        }
        CP_COMMIT();
        CP_WAIT(0);
        __syncthreads();

        // ----- Stage 1: S = Q @ K^T -----
        float sacc[2][4][4];
#pragma unroll
        for (int i = 0; i < 2; i++)
#pragma unroll
            for (int j = 0; j < 4; j++)
#pragma unroll
                for (int r = 0; r < 4; r++) sacc[i][j][r] = 0.0f;

#pragma unroll
        for (int kc = 0; kc < D_; kc += 8) {
            uint32_t a[2][4], bf[4][2];
#pragma unroll
            for (int mi = 0; mi < 2; mi++) {
                const int ab = (wm * 32 + mi * 16 + g) * QPAD + kc + tg;
                a[mi][0] = qs[ab];
                a[mi][1] = qs[ab + 8 * QPAD];
                a[mi][2] = qs[ab + 4];
                a[mi][3] = qs[ab + 8 * QPAD + 4];
            }
#pragma unroll
            for (int ni = 0; ni < 4; ni++) {
                const int bb = (wn * 32 + ni * 8 + g) * QPAD + kc + tg;
                bf[ni][0] = ks[bb];
                bf[ni][1] = ks[bb + 4];
            }
#pragma unroll
            for (int mi = 0; mi < 2; mi++)
#pragma unroll
                for (int ni = 0; ni < 4; ni++)
                    mma8(sacc[mi][ni], a[mi], bf[ni]);
        }

        // silu + mask + store P to smem (raw fp32; mma truncates to tf32)
#pragma unroll
        for (int mi = 0; mi < 2; mi++) {
            const int qr = wm * 32 + mi * 16 + g;
            const int qg0 = q0 + qr, qg1 = qg0 + 8;
            const int iq0 = min(qg0, limit), iq1 = min(qg1, limit);
#pragma unroll
            for (int ni = 0; ni < 4; ni++) {
                const int cc = wn * 32 + ni * 8 + 2 * tg;
                const int kg0 = k0 + cc, kg1 = kg0 + 1;
                const int ik0 = min(kg0, limit), ik1 = min(kg1, limit);

                float p00 = ((qg0 == kg0) || (iq0 > ik0)) ? silu_f(sacc[mi][ni][0] * ALPHA_F) * INV_S_F : 0.0f;
                float p01 = ((qg0 == kg1) || (iq0 > ik1)) ? silu_f(sacc[mi][ni][1] * ALPHA_F) * INV_S_F : 0.0f;
                float p10 = ((qg1 == kg0) || (iq1 > ik0)) ? silu_f(sacc[mi][ni][2] * ALPHA_F) * INV_S_F : 0.0f;
                float p11 = ((qg1 == kg1) || (iq1 > ik1)) ? silu_f(sacc[mi][ni][3] * ALPHA_F) * INV_S_F : 0.0f;

                float2 u0 = {p00, p01};
                float2 u1 = {p10, p11};
                *(float2*)&ps[qr * PPAD + cc] = u0;
                *(float2*)&ps[(qr + 8) * PPAD + cc] = u1;
            }
        }
        __syncthreads();

        // ----- Stage 2: O += P @ V -----
        const uint32_t* psw = (const uint32_t*)ps;
#pragma unroll
        for (int kc = 0; kc < 64; kc += 8) {
            uint32_t a[2][4], bf[8][2];
#pragma unroll
            for (int mi = 0; mi < 2; mi++) {
                const int ab = (wm * 32 + mi * 16 + g) * PPAD + kc + tg;
                a[mi][0] = psw[ab];
                a[mi][1] = psw[ab + 8 * PPAD];
                a[mi][2] = psw[ab + 4];
                a[mi][3] = psw[ab + 8 * PPAD + 4];
            }
#pragma unroll
            for (int ni = 0; ni < 8; ni++) {
                const int bb = (kc + tg) * VPAD + wn * 64 + ni * 8 + g;
                bf[ni][0] = vs[bb];
                bf[ni][1] = vs[bb + 4 * VPAD];
            }
#pragma unroll
            for (int mi = 0; mi < 2; mi++)
#pragma unroll
                for (int ni = 0; ni < 8; ni++)
                    mma8(oacc[mi][ni], a[mi], bf[ni]);
        }
    }

    // Epilogue: write attn output (B*S, H*D)
#pragma unroll
    for (int mi = 0; mi < 2; mi++) {
        const int r1 = q0 + wm * 32 + mi * 16 + g;
#pragma unroll
        for (int ni = 0; ni < 8; ni++) {
            const int c = h * D_ + wn * 64 + ni * 8 + 2 * tg;
            float2 o0 = {oacc[mi][ni][0], oacc[mi][ni][1]};
            float2 o1 = {oacc[mi][ni][2], oacc[mi][ni][3]};
            *(float2*)&g_attn[(size_t)(b * S_ + r1) * E_ + c] = o0;
            *(float2*)&g_attn[(size_t)(b * S_ + r1 + 8) * E_ + c] = o1;
        }
    }
}

// ---------------------------------------------------------------------------
// Launch
// ---------------------------------------------------------------------------
extern "C" void kernel_launch(void* const* d_in, const int* in_sizes, int n_in,
                              void* d_out, int out_size) {
    const float* x        = (const float*)d_in[0];
    const int*   ntg      = (const int*)d_in[1];
    const float* uvqk_w   = (const float*)d_in[2];
    const float* uvqk_b   = (const float*)d_in[3];
    const float* out_w    = (const float*)d_in[4];
    const float* in_scale = (const float*)d_in[5];
    const float* in_bias  = (const float*)d_in[6];
    const float* out_scale= (const float*)d_in[7];
    const float* out_bias = (const float*)d_in[8];
    float* out = (float*)d_out;

    (void)in_sizes; (void)n_in; (void)out_size;

    static bool attr_set = false;
    if (!attr_set) {
        cudaFuncSetAttribute(attn_tc, cudaFuncAttributeMaxDynamicSharedMemorySize,
                             ATTN_SMEM_BYTES);
        attr_set = true;
    }

    ln_in_kernel<<<MTOT, 256>>>(x, in_scale, in_bias);
    gemm_uvqk_tc<<<dim3(UVQK_ / 128, MTOT / 128), 256>>>(uvqk_w, uvqk_b);
    attn_tc<<<dim3(S_ / 128, H_, B_), 256, ATTN_SMEM_BYTES>>>(ntg);
    ln_attn_kernel<<<MTOT, 256>>>(out_scale, out_bias);
    gemm_out_tc<<<dim3(E_ / 128, MTOT / 128), 256>>>(out_w, x, out);
}